// round 13
// baseline (speedup 1.0000x reference)
#include <cuda_runtime.h>
#include <cstdint>
#include <math.h>

#define NPTS 3072
#define NOUT 16
#define ROWS 4           // i-rows per block
#define CH 256           // j-columns per chunk (= blockDim.x)
#define NCH (NPTS / CH)  // 12 chunks per row
#define CHUNK_FLOATS (CH * NOUT)          // 4096 floats = 16 KB
#define CHUNK_BYTES (CHUNK_FLOATS * 4)
#define DEPTH 2          // pipeline depth (2 x 16 KB dynamic smem)
#define GRID (NPTS / ROWS)                // 768 blocks -> ~5 CTAs/SM
#define SMEM_BYTES (DEPTH * CHUNK_BYTES)  // 32 KB

// Single-pass bulk-store kernel, race-free version:
//  - each thread writes ONLY its own 64B slice of the chunk (zeros or values),
//    so there is no cross-thread same-address STS within a sync epoch;
//  - every thread fences generic->async proxy BEFORE the barrier that
//    precedes the TMA bulk store (CUTLASS epilogue pattern).
__global__ __launch_bounds__(256) void bulk_edge_kernel(
    const float* __restrict__ coord,
    const float* __restrict__ sig,
    float* __restrict__ out)
{
    extern __shared__ __align__(16) float buf[];   // DEPTH x CHUNK_FLOATS
    __shared__ float4 s_i[ROWS];        // xi, yi, zi, sqi
    __shared__ float  s_inv[NOUT];      // 1/(2*sigma_c^2), reference rounding
    __shared__ float  s_qden, s_lo, s_hi;

    const int tid = threadIdx.x;
    const int i0  = blockIdx.x * ROWS;

    if (tid < NOUT) {
        float s = sig[tid];
        s_inv[tid] = __fdiv_rn(1.0f, __fmul_rn(__fmul_rn(2.0f, s), s));
    }
    if (tid == 0) {
        float sm = sig[NOUT - 1];
        float qd = __fmul_rn(__fmul_rn(2.0f, sm), sm);
        s_qden = qd;
        s_lo = 0.105300f * qd;   // conservative fast-keep bound
        s_hi = 0.105420f * qd;   // conservative fast-drop bound
    }
    if (tid < ROWS) {
        int ig = i0 + tid;
        float x = coord[3 * ig + 0];
        float y = coord[3 * ig + 1];
        float z = coord[3 * ig + 2];
        float sq = __fadd_rn(__fadd_rn(__fmul_rn(x, x), __fmul_rn(y, y)),
                             __fmul_rn(z, z));
        s_i[tid] = make_float4(x, y, z, sq);
    }
    __syncthreads();

    const float lo = s_lo, hi = s_hi, qden = s_qden;

    unsigned smem_base;
    {
        unsigned a;
        asm("{ .reg .u64 t; cvta.to.shared.u64 t, %1; cvt.u32.u64 %0, t; }"
            : "=r"(a) : "l"(&buf[0]));
        smem_base = a;
    }

    int iter = 0;
    for (int ch = 0; ch < NCH; ch++) {
        // This thread's j for the whole chunk (reused across ROWS i-rows).
        const int j = ch * CH + tid;
        const float xj = coord[3 * j + 0];
        const float yj = coord[3 * j + 1];
        const float zj = coord[3 * j + 2];
        const float sqj = __fadd_rn(__fadd_rn(__fmul_rn(xj, xj), __fmul_rn(yj, yj)),
                                    __fmul_rn(zj, zj));

        for (int r = 0; r < ROWS; r++, iter++) {
            const int b = iter & (DEPTH - 1);
            float* bbuf = buf + (size_t)b * CHUNK_FLOATS;

            // Recycle buffer b: its bulk store from iter-DEPTH must be done.
            if (iter >= DEPTH) {
                if (tid == 0)
                    asm volatile("cp.async.bulk.wait_group %0;"
                                 :: "n"(DEPTH - 1) : "memory");
                __syncthreads();
            }

            // Predicate for pair (i0+r, j) — byte-identical math to prior rounds.
            const int ig = i0 + r;
            const float4 I = s_i[r];
            const float dot = __fmaf_rn(I.z, zj, __fmaf_rn(I.y, yj, __fmul_rn(I.x, xj)));
            float d2 = __fsub_rn(__fadd_rn(I.w, sqj), __fmul_rn(2.0f, dot));
            d2 = fmaxf(d2, 0.0f);

            bool keep;
            if (d2 <= lo) {
                keep = (d2 > 0.0f) && (ig != j);
            } else if (d2 >= hi) {
                keep = false;
            } else {
                const float q = __fdiv_rn(d2, qden);
                if (q <= 0.105340f)       keep = true;
                else if (q >= 0.105380f)  keep = false;
                else                      keep = ((float)exp(-(double)q) >= 0.9f);
                keep = keep && (d2 > 0.0f) && (ig != j);
            }

            // Build this thread's 16 channel values (zeros or Gaussians) and
            // write ONLY the thread-owned 64B slice: no cross-thread races.
            float4 r0 = make_float4(0.f, 0.f, 0.f, 0.f);
            float4 r1 = r0, r2 = r0, r3 = r0;
            if (keep) {
                float v[NOUT];
#pragma unroll
                for (int c = 0; c < NOUT; c++)
                    v[c] = __expf(-__fmul_rn(d2, s_inv[c]));
                r0 = make_float4(v[0],  v[1],  v[2],  v[3]);
                r1 = make_float4(v[4],  v[5],  v[6],  v[7]);
                r2 = make_float4(v[8],  v[9],  v[10], v[11]);
                r3 = make_float4(v[12], v[13], v[14], v[15]);
            }
            float4* dst = reinterpret_cast<float4*>(&bbuf[tid * NOUT]);
            dst[0] = r0;
            dst[1] = r1;
            dst[2] = r2;
            dst[3] = r3;

            // Make this thread's generic-proxy STS visible to the async proxy,
            // THEN barrier, THEN elect tid0 to issue the TMA bulk store.
            asm volatile("fence.proxy.async.shared::cta;" ::: "memory");
            __syncthreads();

            if (tid == 0) {
                float* gdst = out + ((size_t)ig * NPTS + (size_t)ch * CH) * NOUT;
                const unsigned src = smem_base + (unsigned)b * CHUNK_BYTES;
                asm volatile(
                    "cp.async.bulk.global.shared::cta.bulk_group [%0], [%1], %2;"
                    :: "l"(gdst), "r"(src), "n"(CHUNK_BYTES)
                    : "memory");
                asm volatile("cp.async.bulk.commit_group;" ::: "memory");
            }
        }
    }

    // Drain all outstanding bulk stores before the block retires.
    if (tid == 0)
        asm volatile("cp.async.bulk.wait_group 0;" ::: "memory");
    __syncthreads();
}

extern "C" void kernel_launch(void* const* d_in, const int* in_sizes, int n_in,
                              void* d_out, int out_size)
{
    const float* coord = (const float*)d_in[0];   // [3072, 3] fp32
    const float* sig   = (const float*)d_in[1];   // [16] fp32
    float* out = (float*)d_out;                   // [1, 3072, 3072, 16] fp32

    cudaFuncSetAttribute(bulk_edge_kernel,
                         cudaFuncAttributeMaxDynamicSharedMemorySize, SMEM_BYTES);
    bulk_edge_kernel<<<GRID, 256, SMEM_BYTES>>>(coord, sig, out);
}

// round 14
// speedup vs baseline: 1.4416x; 1.4416x over previous
#include <cuda_runtime.h>
#include <cstdint>
#include <math.h>

#define NPTS 3072
#define NOUT 16

// Dense single-pass, one thread per (i,j) pair, output written as two
// 256-bit stores (st.global.v8.f32). Theory: R1's identical structure was
// capped at 4.17 TB/s by L1 store-wavefront throughput (L1=79.9%, DRAM=47.8%);
// STG.256 halves wavefronts per byte -> store stream should approach the
// 7.4 TB/s the driver memset demonstrates on this path.
__global__ __launch_bounds__(256) void dense_v8_kernel(
    const float* __restrict__ coord,
    const float* __restrict__ sig,
    float* __restrict__ out)
{
    __shared__ float s_inv[NOUT];   // 1/(2*sigma_c^2), reference rounding
    __shared__ float s_qden, s_lo, s_hi;

    if (threadIdx.x < NOUT) {
        float s = sig[threadIdx.x];
        s_inv[threadIdx.x] = __fdiv_rn(1.0f, __fmul_rn(__fmul_rn(2.0f, s), s));
    }
    if (threadIdx.x == 0) {
        float sm = sig[NOUT - 1];
        float qd = __fmul_rn(__fmul_rn(2.0f, sm), sm);
        s_qden = qd;
        s_lo = 0.105300f * qd;   // conservative fast-keep bound
        s_hi = 0.105420f * qd;   // conservative fast-drop bound
    }
    __syncthreads();

    const int j = blockIdx.x * blockDim.x + threadIdx.x;
    const int i = blockIdx.y;

    const float xi = __ldg(coord + 3 * i + 0);
    const float yi = __ldg(coord + 3 * i + 1);
    const float zi = __ldg(coord + 3 * i + 2);
    const float xj = __ldg(coord + 3 * j + 0);
    const float yj = __ldg(coord + 3 * j + 1);
    const float zj = __ldg(coord + 3 * j + 2);

    // sq = (x*x + y*y) + z*z, no fma contraction (matches XLA reduce order)
    const float sqi = __fadd_rn(__fadd_rn(__fmul_rn(xi, xi), __fmul_rn(yi, yi)),
                                __fmul_rn(zi, zi));
    const float sqj = __fadd_rn(__fadd_rn(__fmul_rn(xj, xj), __fmul_rn(yj, yj)),
                                __fmul_rn(zj, zj));
    // dot via ascending-k fma chain (matches host fma path)
    const float dot = __fmaf_rn(zi, zj, __fmaf_rn(yi, yj, __fmul_rn(xi, xj)));

    float d2 = __fsub_rn(__fadd_rn(sqi, sqj), __fmul_rn(2.0f, dot));
    d2 = fmaxf(d2, 0.0f);

    // keep = (exp(-d2/(2*smax^2)) >= 0.9) && d2 > 0 && i != j
    bool keep;
    if (d2 <= s_lo) {
        keep = (d2 > 0.0f) && (i != j);
    } else if (d2 >= s_hi) {
        keep = false;
    } else {
        // boundary band: reproduce reference predicate exactly
        const float q = __fdiv_rn(d2, s_qden);
        if (q <= 0.105340f)       keep = true;
        else if (q >= 0.105380f)  keep = false;
        else                      keep = ((float)exp(-(double)q) >= 0.9f);
        keep = keep && (d2 > 0.0f) && (i != j);
    }

    float v[NOUT];
#pragma unroll
    for (int c = 0; c < NOUT; c++) v[c] = 0.0f;
    if (keep) {
#pragma unroll
        for (int c = 0; c < NOUT; c++)
            v[c] = __expf(-__fmul_rn(d2, s_inv[c]));
    }

    float* base = out + ((size_t)i * NPTS + j) * NOUT;   // 64B-aligned
    asm volatile(
        "st.global.v8.f32 [%0], {%1,%2,%3,%4,%5,%6,%7,%8};"
        :: "l"(base),
           "f"(v[0]), "f"(v[1]), "f"(v[2]), "f"(v[3]),
           "f"(v[4]), "f"(v[5]), "f"(v[6]), "f"(v[7])
        : "memory");
    asm volatile(
        "st.global.v8.f32 [%0], {%1,%2,%3,%4,%5,%6,%7,%8};"
        :: "l"(base + 8),
           "f"(v[8]),  "f"(v[9]),  "f"(v[10]), "f"(v[11]),
           "f"(v[12]), "f"(v[13]), "f"(v[14]), "f"(v[15])
        : "memory");
}

extern "C" void kernel_launch(void* const* d_in, const int* in_sizes, int n_in,
                              void* d_out, int out_size)
{
    const float* coord = (const float*)d_in[0];   // [3072, 3] fp32
    const float* sig   = (const float*)d_in[1];   // [16] fp32
    float* out = (float*)d_out;                   // [1, 3072, 3072, 16] fp32

    dim3 block(256);
    dim3 grid(NPTS / 256, NPTS);   // (12, 3072) — R1's 85%-occupancy shape
    dense_v8_kernel<<<grid, block>>>(coord, sig, out);
}

// round 15
// speedup vs baseline: 1.4516x; 1.0069x over previous
#include <cuda_runtime.h>
#include <cstdint>
#include <math.h>

#define NPTS 3072
#define NOUT 16
#define RPT 2            // i-rows per thread

// Dense single-pass with 256-bit streaming stores. R14 (one row/thread,
// plain st.global.v8) hit 6.71 TB/s / 83.8us. This round: amortize j-coord
// loads + predicate setup over 2 i-rows and use .cs (evict-first) stores.
__global__ __launch_bounds__(256) void dense_v8_kernel(
    const float* __restrict__ coord,
    const float* __restrict__ sig,
    float* __restrict__ out)
{
    __shared__ float s_inv[NOUT];   // 1/(2*sigma_c^2), reference rounding
    __shared__ float s_qden, s_lo, s_hi;

    if (threadIdx.x < NOUT) {
        float s = sig[threadIdx.x];
        s_inv[threadIdx.x] = __fdiv_rn(1.0f, __fmul_rn(__fmul_rn(2.0f, s), s));
    }
    if (threadIdx.x == 0) {
        float sm = sig[NOUT - 1];
        float qd = __fmul_rn(__fmul_rn(2.0f, sm), sm);
        s_qden = qd;
        s_lo = 0.105300f * qd;   // conservative fast-keep bound
        s_hi = 0.105420f * qd;   // conservative fast-drop bound
    }
    __syncthreads();

    const int j  = blockIdx.x * blockDim.x + threadIdx.x;
    const int i0 = blockIdx.y * RPT;

    const float xj = __ldg(coord + 3 * j + 0);
    const float yj = __ldg(coord + 3 * j + 1);
    const float zj = __ldg(coord + 3 * j + 2);
    const float sqj = __fadd_rn(__fadd_rn(__fmul_rn(xj, xj), __fmul_rn(yj, yj)),
                                __fmul_rn(zj, zj));

    const float lo = s_lo, hi = s_hi, qden = s_qden;

#pragma unroll
    for (int r = 0; r < RPT; r++) {
        const int i = i0 + r;
        const float xi = __ldg(coord + 3 * i + 0);
        const float yi = __ldg(coord + 3 * i + 1);
        const float zi = __ldg(coord + 3 * i + 2);

        // sq = (x*x + y*y) + z*z, no fma contraction (matches reference)
        const float sqi = __fadd_rn(__fadd_rn(__fmul_rn(xi, xi), __fmul_rn(yi, yi)),
                                    __fmul_rn(zi, zi));
        // dot via ascending-k fma chain (matches host fma path)
        const float dot = __fmaf_rn(zi, zj, __fmaf_rn(yi, yj, __fmul_rn(xi, xj)));

        float d2 = __fsub_rn(__fadd_rn(sqi, sqj), __fmul_rn(2.0f, dot));
        d2 = fmaxf(d2, 0.0f);

        // keep = (exp(-d2/(2*smax^2)) >= 0.9) && d2 > 0 && i != j
        bool keep;
        if (d2 <= lo) {
            keep = (d2 > 0.0f) && (i != j);
        } else if (d2 >= hi) {
            keep = false;
        } else {
            // boundary band: reproduce reference predicate exactly
            const float q = __fdiv_rn(d2, qden);
            if (q <= 0.105340f)       keep = true;
            else if (q >= 0.105380f)  keep = false;
            else                      keep = ((float)exp(-(double)q) >= 0.9f);
            keep = keep && (d2 > 0.0f) && (i != j);
        }

        float v[NOUT];
#pragma unroll
        for (int c = 0; c < NOUT; c++) v[c] = 0.0f;
        if (keep) {
#pragma unroll
            for (int c = 0; c < NOUT; c++)
                v[c] = __expf(-__fmul_rn(d2, s_inv[c]));
        }

        float* base = out + ((size_t)i * NPTS + j) * NOUT;   // 64B-aligned
        asm volatile(
            "st.global.cs.v8.f32 [%0], {%1,%2,%3,%4,%5,%6,%7,%8};"
            :: "l"(base),
               "f"(v[0]), "f"(v[1]), "f"(v[2]), "f"(v[3]),
               "f"(v[4]), "f"(v[5]), "f"(v[6]), "f"(v[7])
            : "memory");
        asm volatile(
            "st.global.cs.v8.f32 [%0], {%1,%2,%3,%4,%5,%6,%7,%8};"
            :: "l"(base + 8),
               "f"(v[8]),  "f"(v[9]),  "f"(v[10]), "f"(v[11]),
               "f"(v[12]), "f"(v[13]), "f"(v[14]), "f"(v[15])
            : "memory");
    }
}

extern "C" void kernel_launch(void* const* d_in, const int* in_sizes, int n_in,
                              void* d_out, int out_size)
{
    const float* coord = (const float*)d_in[0];   // [3072, 3] fp32
    const float* sig   = (const float*)d_in[1];   // [16] fp32
    float* out = (float*)d_out;                   // [1, 3072, 3072, 16] fp32

    dim3 block(256);
    dim3 grid(NPTS / 256, NPTS / RPT);   // (12, 1536)
    dense_v8_kernel<<<grid, block>>>(coord, sig, out);
}

// round 16
// speedup vs baseline: 1.4668x; 1.0105x over previous
#include <cuda_runtime.h>
#include <cstdint>
#include <math.h>

#define NPTS 3072
#define NOUT 16

// Dense single-pass, one thread per (i,j) pair, two 256-bit streaming stores.
// At the measured HBM write floor (604MB / ~81.8us = 7.39 TB/s ~= driver
// memset's 7.45). This round: best-occupancy shape (1 row/thread) + .cs +
// 512-thread blocks to shave wave-boundary bubbles.
__global__ __launch_bounds__(512) void dense_v8_kernel(
    const float* __restrict__ coord,
    const float* __restrict__ sig,
    float* __restrict__ out)
{
    __shared__ float s_inv[NOUT];   // 1/(2*sigma_c^2), reference rounding
    __shared__ float s_qden, s_lo, s_hi;

    if (threadIdx.x < NOUT) {
        float s = sig[threadIdx.x];
        s_inv[threadIdx.x] = __fdiv_rn(1.0f, __fmul_rn(__fmul_rn(2.0f, s), s));
    }
    if (threadIdx.x == 0) {
        float sm = sig[NOUT - 1];
        float qd = __fmul_rn(__fmul_rn(2.0f, sm), sm);
        s_qden = qd;
        s_lo = 0.105300f * qd;   // conservative fast-keep bound
        s_hi = 0.105420f * qd;   // conservative fast-drop bound
    }
    __syncthreads();

    const int jj = blockIdx.x * blockDim.x + threadIdx.x;  // 0..2*NPTS-1
    const int i  = blockIdx.y * 2 + (jj >= NPTS ? 1 : 0);
    const int j  = (jj >= NPTS) ? (jj - NPTS) : jj;

    const float xi = __ldg(coord + 3 * i + 0);
    const float yi = __ldg(coord + 3 * i + 1);
    const float zi = __ldg(coord + 3 * i + 2);
    const float xj = __ldg(coord + 3 * j + 0);
    const float yj = __ldg(coord + 3 * j + 1);
    const float zj = __ldg(coord + 3 * j + 2);

    // sq = (x*x + y*y) + z*z, no fma contraction (matches reference)
    const float sqi = __fadd_rn(__fadd_rn(__fmul_rn(xi, xi), __fmul_rn(yi, yi)),
                                __fmul_rn(zi, zi));
    const float sqj = __fadd_rn(__fadd_rn(__fmul_rn(xj, xj), __fmul_rn(yj, yj)),
                                __fmul_rn(zj, zj));
    // dot via ascending-k fma chain (matches host fma path)
    const float dot = __fmaf_rn(zi, zj, __fmaf_rn(yi, yj, __fmul_rn(xi, xj)));

    float d2 = __fsub_rn(__fadd_rn(sqi, sqj), __fmul_rn(2.0f, dot));
    d2 = fmaxf(d2, 0.0f);

    // keep = (exp(-d2/(2*smax^2)) >= 0.9) && d2 > 0 && i != j
    bool keep;
    if (d2 <= s_lo) {
        keep = (d2 > 0.0f) && (i != j);
    } else if (d2 >= s_hi) {
        keep = false;
    } else {
        // boundary band: reproduce reference predicate exactly
        const float q = __fdiv_rn(d2, s_qden);
        if (q <= 0.105340f)       keep = true;
        else if (q >= 0.105380f)  keep = false;
        else                      keep = ((float)exp(-(double)q) >= 0.9f);
        keep = keep && (d2 > 0.0f) && (i != j);
    }

    float v[NOUT];
#pragma unroll
    for (int c = 0; c < NOUT; c++) v[c] = 0.0f;
    if (keep) {
#pragma unroll
        for (int c = 0; c < NOUT; c++)
            v[c] = __expf(-__fmul_rn(d2, s_inv[c]));
    }

    float* base = out + ((size_t)i * NPTS + j) * NOUT;   // 64B-aligned
    asm volatile(
        "st.global.cs.v8.f32 [%0], {%1,%2,%3,%4,%5,%6,%7,%8};"
        :: "l"(base),
           "f"(v[0]), "f"(v[1]), "f"(v[2]), "f"(v[3]),
           "f"(v[4]), "f"(v[5]), "f"(v[6]), "f"(v[7])
        : "memory");
    asm volatile(
        "st.global.cs.v8.f32 [%0], {%1,%2,%3,%4,%5,%6,%7,%8};"
        :: "l"(base + 8),
           "f"(v[8]),  "f"(v[9]),  "f"(v[10]), "f"(v[11]),
           "f"(v[12]), "f"(v[13]), "f"(v[14]), "f"(v[15])
        : "memory");
}

extern "C" void kernel_launch(void* const* d_in, const int* in_sizes, int n_in,
                              void* d_out, int out_size)
{
    const float* coord = (const float*)d_in[0];   // [3072, 3] fp32
    const float* sig   = (const float*)d_in[1];   // [16] fp32
    float* out = (float*)d_out;                   // [1, 3072, 3072, 16] fp32

    // 512-thread blocks, each covering 2 full i-rows' worth of pairs.
    dim3 block(512);
    dim3 grid((2 * NPTS) / 512, NPTS / 2);   // (12, 1536) = 18432 blocks
    dense_v8_kernel<<<grid, block>>>(coord, sig, out);
}